// round 1
// baseline (speedup 1.0000x reference)
#include <cuda_runtime.h>
#include <cstdint>

// Problem constants (GraphConvolution_37915971289734):
//   x: (B=4, N=50000, C=128) f32
//   adj_indices: (2, E=800000) i32   [row ; col]
//   adj_values:  (E,) f32
//   W: (128, 128) f32   b: (128,) f32
//   out: (B, N, 128) f32
// y = A @ (x @ W^T) + b   (linearity lets us do the GEMM first)

#define C_DIM 128
#define B_DIM 4

// Scratch for z = x @ W^T : B*N*C floats = 25.6M (102.4 MB), static device array.
__device__ float g_z[(size_t)B_DIM * 50000 * C_DIM];

// ---------------------------------------------------------------------------
// Kernel 1: z = x @ W^T   (M = B*N rows, K = C = 128, Nout = 128)
// BM=64 rows per block, BN=128 (all outputs), full K in smem.
// 256 threads: 16x16, each computes TM=4 rows x TN=8 cols.
// ---------------------------------------------------------------------------
#define BM 64
#define BN 128

__global__ __launch_bounds__(256, 2)
void gemm_xwT(const float* __restrict__ x, const float* __restrict__ W,
              float* __restrict__ z) {
    extern __shared__ float smem[];
    float* Xs = smem;              // [K=128][BM]   Xs[k*BM + row]
    float* Ws = smem + 128 * BM;   // [K=128][BN]   Ws[k*BN + o]

    const int tid = threadIdx.x;
    const size_t m0 = (size_t)blockIdx.x * BM;

    // Load X tile (64 rows x 128 k) transposed into Xs[k][row]
    #pragma unroll
    for (int idx = tid; idx < BM * 32; idx += 256) {
        int row = idx >> 5;
        int kq  = idx & 31;
        float4 v = *(const float4*)(x + (m0 + row) * C_DIM + kq * 4);
        Xs[(kq * 4 + 0) * BM + row] = v.x;
        Xs[(kq * 4 + 1) * BM + row] = v.y;
        Xs[(kq * 4 + 2) * BM + row] = v.z;
        Xs[(kq * 4 + 3) * BM + row] = v.w;
    }
    // Load W (128 x 128, o-major) transposed into Ws[k][o]
    #pragma unroll
    for (int idx = tid; idx < 128 * 32; idx += 256) {
        int o  = idx >> 5;
        int kq = idx & 31;
        float4 v = *(const float4*)(W + o * C_DIM + kq * 4);
        Ws[(kq * 4 + 0) * BN + o] = v.x;
        Ws[(kq * 4 + 1) * BN + o] = v.y;
        Ws[(kq * 4 + 2) * BN + o] = v.z;
        Ws[(kq * 4 + 3) * BN + o] = v.w;
    }
    __syncthreads();

    const int tx = tid & 15;         // 16 col-groups of 8
    const int ty = tid >> 4;         // 16 row-groups of 4
    const int r0 = ty * 4;
    const int c0 = tx * 8;

    float acc[4][8];
    #pragma unroll
    for (int i = 0; i < 4; i++)
        #pragma unroll
        for (int j = 0; j < 8; j++) acc[i][j] = 0.0f;

    #pragma unroll 8
    for (int k = 0; k < 128; k++) {
        float4 a  = *(const float4*)(Xs + k * BM + r0);
        float4 b0 = *(const float4*)(Ws + k * BN + c0);
        float4 b1 = *(const float4*)(Ws + k * BN + c0 + 4);
        float av[4] = {a.x, a.y, a.z, a.w};
        float bv[8] = {b0.x, b0.y, b0.z, b0.w, b1.x, b1.y, b1.z, b1.w};
        #pragma unroll
        for (int i = 0; i < 4; i++)
            #pragma unroll
            for (int j = 0; j < 8; j++)
                acc[i][j] = fmaf(av[i], bv[j], acc[i][j]);
    }

    #pragma unroll
    for (int i = 0; i < 4; i++) {
        float* dst = z + (m0 + r0 + i) * C_DIM + c0;
        *(float4*)(dst)     = make_float4(acc[i][0], acc[i][1], acc[i][2], acc[i][3]);
        *(float4*)(dst + 4) = make_float4(acc[i][4], acc[i][5], acc[i][6], acc[i][7]);
    }
}

// ---------------------------------------------------------------------------
// Kernel 2: out[b,n,:] = bias[:]
// ---------------------------------------------------------------------------
__global__ void init_bias(float* __restrict__ out, const float* __restrict__ bias,
                          size_t n_vec4) {
    size_t i = (size_t)blockIdx.x * blockDim.x + threadIdx.x;
    if (i >= n_vec4) return;
    int q = (int)(i & 31);  // which float4 within a 128-channel row
    float4 bv = ((const float4*)bias)[q];
    ((float4*)out)[i] = bv;
}

// ---------------------------------------------------------------------------
// Kernel 3: scatter-add.  One warp per edge; loop over 4 batches.
// out[b, row, :] += v * z[b, col, :]   via red.global.add.v4.f32
// ---------------------------------------------------------------------------
__global__ __launch_bounds__(256)
void spmm_scatter(const float* __restrict__ z,
                  const int* __restrict__ rows, const int* __restrict__ cols,
                  const float* __restrict__ vals,
                  float* __restrict__ out, int E, int N) {
    int gtid = blockIdx.x * blockDim.x + threadIdx.x;
    int e    = gtid >> 5;
    int lane = gtid & 31;
    if (e >= E) return;

    const int r = rows[e];
    const int c = cols[e];
    const float v = vals[e];

    #pragma unroll
    for (int b = 0; b < B_DIM; b++) {
        const float4* src = (const float4*)(z + ((size_t)b * N + c) * C_DIM);
        float4 m = src[lane];
        m.x *= v; m.y *= v; m.z *= v; m.w *= v;
        float* dst = out + ((size_t)b * N + r) * C_DIM + lane * 4;
        asm volatile("red.global.add.v4.f32 [%0], {%1, %2, %3, %4};"
                     :: "l"(dst), "f"(m.x), "f"(m.y), "f"(m.z), "f"(m.w)
                     : "memory");
    }
}

// ---------------------------------------------------------------------------
extern "C" void kernel_launch(void* const* d_in, const int* in_sizes, int n_in,
                              void* d_out, int out_size) {
    const float* x    = (const float*)d_in[0];
    const int*   adj  = (const int*)d_in[1];
    const float* vals = (const float*)d_in[2];
    const float* W    = (const float*)d_in[3];
    const float* bias = (const float*)d_in[4];
    float* out = (float*)d_out;

    const int E = in_sizes[2];
    const int N = in_sizes[0] / (B_DIM * C_DIM);
    const size_t M = (size_t)B_DIM * N;

    const int* rows = adj;
    const int* cols = adj + E;

    float* z;
    cudaGetSymbolAddress((void**)&z, g_z);

    // GEMM: z = x @ W^T
    static bool attr_set = false;
    const int smem_bytes = (128 * BM + 128 * BN) * sizeof(float);  // 98304
    if (!attr_set) {
        cudaFuncSetAttribute(gemm_xwT, cudaFuncAttributeMaxDynamicSharedMemorySize,
                             smem_bytes);
        attr_set = true;
    }
    gemm_xwT<<<(int)(M / BM), 256, smem_bytes>>>(x, W, z);

    // out = bias
    size_t n_vec4 = M * (C_DIM / 4);
    init_bias<<<(int)((n_vec4 + 255) / 256), 256>>>(out, bias, n_vec4);

    // scatter
    long long total_threads = (long long)E * 32;
    int blocks = (int)((total_threads + 255) / 256);
    spmm_scatter<<<blocks, 256>>>(z, rows, cols, vals, out, E, N);
}

// round 2
// speedup vs baseline: 1.7741x; 1.7741x over previous
#include <cuda_runtime.h>
#include <cstdint>

// GraphConvolution: y = A @ (x @ W^T) + b
//   x: (B=4, N=50000, C=128) f32, adj: (2, E=800000) i32, vals: (E,) f32
//   W: (128,128) f32, b: (128,) f32, out: (B,N,128) f32

#define C_DIM 128
#define B_DIM 4
#define N_ROWS 50000
#define E_MAX  800000

// Scratch (static device arrays; no allocs allowed)
__device__ float g_z[(size_t)B_DIM * N_ROWS * C_DIM];     // z = x @ W^T
__device__ int   g_cnt[N_ROWS];                            // per-row edge count
__device__ int   g_rowptr[N_ROWS + 1];
__device__ int   g_ofs[N_ROWS];                            // fill cursors
__device__ float2 g_edata[E_MAX];                          // (col_as_float_bits, val) per CSR slot

// ---------------------------------------------------------------------------
// GEMM: z = x @ W^T.  M=B*N rows, K=128, 128 outputs.
// BM=64 rows/block, BN=128, full K resident. 256 threads, 4x8 micro-tile.
// Conflict-free smem: Xs[m][k] pad 132 (direct float4 store, coalesced load),
// Ws[k][c] pad 132 (register-transposed store, lane varies c -> conflict-free).
// ---------------------------------------------------------------------------
#define BM 64
#define BN 128
#define XPAD 132

__global__ __launch_bounds__(256, 2)
void gemm_xwT(const float* __restrict__ x, const float* __restrict__ W,
              float* __restrict__ z, int M) {
    extern __shared__ float smem[];
    float* Xs = smem;                 // [BM][XPAD]
    float* Ws = smem + BM * XPAD;     // [128][XPAD]  (k-major)

    const int tid = threadIdx.x;
    const long long m0 = (long long)blockIdx.x * BM;

    // --- Stage X tile: Xs[m][k]. Warp reads one full 512B row -> coalesced.
    // STS float4 at m*XPAD + lane*4 -> conflict-free.
    #pragma unroll
    for (int it = 0; it < 8; it++) {
        int idx = tid + it * 256;          // 0..2047
        int m   = idx >> 5;                // 0..63
        int kq  = idx & 31;                // float4 index 0..31
        long long gm = m0 + m; if (gm >= M) gm = M - 1;   // clamp (stores guarded)
        float4 v = *(const float4*)(x + gm * C_DIM + kq * 4);
        *(float4*)(Xs + m * XPAD + kq * 4) = v;
    }
    // --- Stage W transposed: Ws[k][o]. lane varies o -> STS stride 1, conflict-free.
    #pragma unroll
    for (int it = 0; it < 16; it++) {
        int idx = tid + it * 256;          // 0..4095
        int o   = idx & 127;               // varies with lane
        int kq  = idx >> 7;                // 0..31, fixed per warp
        float4 v = *(const float4*)(W + o * C_DIM + kq * 4);
        Ws[(kq * 4 + 0) * XPAD + o] = v.x;
        Ws[(kq * 4 + 1) * XPAD + o] = v.y;
        Ws[(kq * 4 + 2) * XPAD + o] = v.z;
        Ws[(kq * 4 + 3) * XPAD + o] = v.w;
    }
    __syncthreads();

    const int tx = tid & 15;           // 16 col-groups of 8
    const int ty = tid >> 4;           // 16 row-groups of 4
    const int r0 = ty * 4;
    const int c0 = tx * 8;

    float acc[4][8];
    #pragma unroll
    for (int i = 0; i < 4; i++)
        #pragma unroll
        for (int j = 0; j < 8; j++) acc[i][j] = 0.0f;

    const float* xr0 = Xs + r0 * XPAD;

    #pragma unroll 4
    for (int k = 0; k < 128; k++) {
        // A: 4 broadcast scalars (2 distinct addrs/warp -> no conflicts)
        float a0 = xr0[0 * XPAD + k];
        float a1 = xr0[1 * XPAD + k];
        float a2 = xr0[2 * XPAD + k];
        float a3 = xr0[3 * XPAD + k];
        // B: 2x float4, k-major
        float4 b0 = *(const float4*)(Ws + k * XPAD + c0);
        float4 b1 = *(const float4*)(Ws + k * XPAD + c0 + 4);
        float bv[8] = {b0.x, b0.y, b0.z, b0.w, b1.x, b1.y, b1.z, b1.w};
        #pragma unroll
        for (int j = 0; j < 8; j++) {
            acc[0][j] = fmaf(a0, bv[j], acc[0][j]);
            acc[1][j] = fmaf(a1, bv[j], acc[1][j]);
            acc[2][j] = fmaf(a2, bv[j], acc[2][j]);
            acc[3][j] = fmaf(a3, bv[j], acc[3][j]);
        }
    }

    #pragma unroll
    for (int i = 0; i < 4; i++) {
        long long gm = m0 + r0 + i;
        if (gm < M) {
            float* dst = z + gm * C_DIM + c0;
            *(float4*)(dst)     = make_float4(acc[i][0], acc[i][1], acc[i][2], acc[i][3]);
            *(float4*)(dst + 4) = make_float4(acc[i][4], acc[i][5], acc[i][6], acc[i][7]);
        }
    }
}

// ---------------------------------------------------------------------------
// CSR build
// ---------------------------------------------------------------------------
__global__ void k_zero_cnt(int n) {
    int i = blockIdx.x * blockDim.x + threadIdx.x;
    if (i < n) g_cnt[i] = 0;
}

__global__ void k_count(const int* __restrict__ rows, int E) {
    int e = blockIdx.x * blockDim.x + threadIdx.x;
    if (e < E) atomicAdd(&g_cnt[rows[e]], 1);
}

// Single block, 1024 threads: chunked serial + block scan.
#define SCAN_T 1024
__global__ __launch_bounds__(SCAN_T)
void k_scan(int n, int E) {
    __shared__ int s[SCAN_T];
    const int t = threadIdx.x;
    const int chunk = (n + SCAN_T - 1) / SCAN_T;
    const int base = t * chunk;
    int sum = 0;
    for (int j = 0; j < chunk; j++) {
        int r = base + j;
        if (r < n) sum += g_cnt[r];
    }
    s[t] = sum;
    __syncthreads();
    // inclusive Hillis-Steele
    #pragma unroll
    for (int d = 1; d < SCAN_T; d <<= 1) {
        int v = (t >= d) ? s[t - d] : 0;
        __syncthreads();
        s[t] += v;
        __syncthreads();
    }
    int run = s[t] - sum;  // exclusive prefix
    for (int j = 0; j < chunk; j++) {
        int r = base + j;
        if (r < n) {
            g_rowptr[r] = run;
            g_ofs[r]    = run;
            run += g_cnt[r];
        }
    }
    if (t == 0) g_rowptr[n] = E;
}

__global__ void k_fill(const int* __restrict__ rows, const int* __restrict__ cols,
                       const float* __restrict__ vals, int E) {
    int e = blockIdx.x * blockDim.x + threadIdx.x;
    if (e >= E) return;
    int r = rows[e];
    int pos = atomicAdd(&g_ofs[r], 1);
    float2 ed;
    ed.x = __int_as_float(cols[e]);
    ed.y = vals[e];
    g_edata[pos] = ed;
}

// ---------------------------------------------------------------------------
// Gather: one warp per output row, all 4 batches in registers, bias fused.
// out[b,r,:] = bias + sum_e vals[e] * z[b, cols[e], :]
// ---------------------------------------------------------------------------
__global__ __launch_bounds__(256)
void k_gather(const float* __restrict__ z, const float* __restrict__ bias,
              float* __restrict__ out, int N) {
    int gw   = (blockIdx.x * blockDim.x + threadIdx.x) >> 5;
    int lane = threadIdx.x & 31;
    if (gw >= N) return;
    const int r = gw;

    float4 acc0 = make_float4(0.f, 0.f, 0.f, 0.f);
    float4 acc1 = acc0, acc2 = acc0, acc3 = acc0;

    const int start = g_rowptr[r];
    const int end   = g_rowptr[r + 1];
    const size_t NB = (size_t)N * 32;   // float4 units per batch

    for (int i = start; i < end; i++) {
        float2 ed = g_edata[i];                 // sequential, uniform
        int   c = __float_as_int(ed.x);
        float v = ed.y;
        const float4* src = (const float4*)z + (size_t)c * 32 + lane;
        float4 z0 = src[0];
        float4 z1 = src[NB];
        float4 z2 = src[2 * NB];
        float4 z3 = src[3 * NB];
        acc0.x = fmaf(v, z0.x, acc0.x); acc0.y = fmaf(v, z0.y, acc0.y);
        acc0.z = fmaf(v, z0.z, acc0.z); acc0.w = fmaf(v, z0.w, acc0.w);
        acc1.x = fmaf(v, z1.x, acc1.x); acc1.y = fmaf(v, z1.y, acc1.y);
        acc1.z = fmaf(v, z1.z, acc1.z); acc1.w = fmaf(v, z1.w, acc1.w);
        acc2.x = fmaf(v, z2.x, acc2.x); acc2.y = fmaf(v, z2.y, acc2.y);
        acc2.z = fmaf(v, z2.z, acc2.z); acc2.w = fmaf(v, z2.w, acc2.w);
        acc3.x = fmaf(v, z3.x, acc3.x); acc3.y = fmaf(v, z3.y, acc3.y);
        acc3.z = fmaf(v, z3.z, acc3.z); acc3.w = fmaf(v, z3.w, acc3.w);
    }

    float4 bv = ((const float4*)bias)[lane];
    acc0.x += bv.x; acc0.y += bv.y; acc0.z += bv.z; acc0.w += bv.w;
    acc1.x += bv.x; acc1.y += bv.y; acc1.z += bv.z; acc1.w += bv.w;
    acc2.x += bv.x; acc2.y += bv.y; acc2.z += bv.z; acc2.w += bv.w;
    acc3.x += bv.x; acc3.y += bv.y; acc3.z += bv.z; acc3.w += bv.w;

    float4* dst = (float4*)out + (size_t)r * 32 + lane;
    dst[0]      = acc0;
    dst[NB]     = acc1;
    dst[2 * NB] = acc2;
    dst[3 * NB] = acc3;
}

// ---------------------------------------------------------------------------
extern "C" void kernel_launch(void* const* d_in, const int* in_sizes, int n_in,
                              void* d_out, int out_size) {
    const float* x    = (const float*)d_in[0];
    const int*   adj  = (const int*)d_in[1];
    const float* vals = (const float*)d_in[2];
    const float* W    = (const float*)d_in[3];
    const float* bias = (const float*)d_in[4];
    float* out = (float*)d_out;

    const int E = in_sizes[2];
    const int N = in_sizes[0] / (B_DIM * C_DIM);
    const int M = B_DIM * N;

    const int* rows = adj;
    const int* cols = adj + E;

    float* z;
    cudaGetSymbolAddress((void**)&z, g_z);

    // CSR build
    k_zero_cnt<<<(N + 255) / 256, 256>>>(N);
    k_count<<<(E + 255) / 256, 256>>>(rows, E);
    k_scan<<<1, SCAN_T>>>(N, E);
    k_fill<<<(E + 255) / 256, 256>>>(rows, cols, vals, E);

    // GEMM
    static bool attr_set = false;
    const int smem_bytes = (BM * XPAD + 128 * XPAD) * sizeof(float);  // 101376
    if (!attr_set) {
        cudaFuncSetAttribute(gemm_xwT, cudaFuncAttributeMaxDynamicSharedMemorySize,
                             smem_bytes);
        attr_set = true;
    }
    gemm_xwT<<<(M + BM - 1) / BM, 256, smem_bytes>>>(x, W, z, M);

    // Gather with fused bias
    int warps = N;
    int blocks = (warps * 32 + 255) / 256;
    k_gather<<<blocks, 256>>>(z, bias, out, N);
}

// round 4
// speedup vs baseline: 2.5174x; 1.4190x over previous
#include <cuda_runtime.h>
#include <mma.h>
#include <cstdint>

using namespace nvcuda;

// GraphConvolution: y = A @ (x @ W^T) + b
//   x: (B=4, N=50000, C=128) f32, adj: (2, E=800000) i32, vals: (E,) f32
//   W: (128,128) f32, b: (128,) f32, out: (B,N,128) f32

#define C_DIM 128
#define B_DIM 4
#define N_ROWS 50000
#define E_MAX  800000

__device__ float  g_z[(size_t)B_DIM * N_ROWS * C_DIM];
__device__ int    g_cnt[N_ROWS];
__device__ int    g_rowptr[N_ROWS + 1];
__device__ int    g_ofs[N_ROWS];
__device__ float2 g_edata[E_MAX];

// ===========================================================================
// GEMM z = x @ W^T via wmma tf32 (m16n16k8).
// CTA tile: 128(m) x 128(n) x 128(k). 8 warps in 2(m) x 4(n) grid;
// each warp: 64x32 = 4 m-frags x 2 n-frags. A/B tf32 in smem, pad 136.
// ===========================================================================
#define LDA 136
#define GEMM_SMEM (2 * 128 * LDA * 4)   // 139264 bytes

__global__ __launch_bounds__(256, 1)
void gemm_wmma(const float* __restrict__ x, const float* __restrict__ W,
               float* __restrict__ z, int M) {
    extern __shared__ float smem[];
    float* As = smem;               // [128][LDA]  x rows (tf32)
    float* Bs = smem + 128 * LDA;   // [128][LDA]  W rows (tf32), row o, col k

    const int tid = threadIdx.x;
    const int wid = tid >> 5;
    const long long m0 = (long long)blockIdx.x * 128;

    // Stage A (x tile) and B (W), converting to tf32. Coalesced float4 loads,
    // conflict-free float4 stores (row stride 136 = 4 mod 32 banks).
    #pragma unroll
    for (int it = 0; it < 16; it++) {
        int idx = tid + it * 256;       // 0..4095
        int row = idx >> 5;             // 0..127
        int kq  = idx & 31;             // float4 index
        long long gm = m0 + row; if (gm >= M) gm = M - 1;
        float4 v = *(const float4*)(x + gm * C_DIM + kq * 4);
        v.x = wmma::__float_to_tf32(v.x); v.y = wmma::__float_to_tf32(v.y);
        v.z = wmma::__float_to_tf32(v.z); v.w = wmma::__float_to_tf32(v.w);
        *(float4*)(As + row * LDA + kq * 4) = v;
    }
    #pragma unroll
    for (int it = 0; it < 16; it++) {
        int idx = tid + it * 256;
        int row = idx >> 5;
        int kq  = idx & 31;
        float4 v = *(const float4*)(W + row * C_DIM + kq * 4);
        v.x = wmma::__float_to_tf32(v.x); v.y = wmma::__float_to_tf32(v.y);
        v.z = wmma::__float_to_tf32(v.z); v.w = wmma::__float_to_tf32(v.w);
        *(float4*)(Bs + row * LDA + kq * 4) = v;
    }
    __syncthreads();

    const int wm = wid & 1;    // 0..1  -> m offset wm*64
    const int wn = wid >> 1;   // 0..3  -> n offset wn*32

    wmma::fragment<wmma::accumulator, 16, 16, 8, float> acc[4][2];
    #pragma unroll
    for (int i = 0; i < 4; i++)
        #pragma unroll
        for (int j = 0; j < 2; j++) wmma::fill_fragment(acc[i][j], 0.0f);

    #pragma unroll
    for (int ks = 0; ks < 16; ks++) {
        const int k = ks * 8;
        wmma::fragment<wmma::matrix_a, 16, 16, 8, wmma::precision::tf32,
                       wmma::row_major> a[4];
        wmma::fragment<wmma::matrix_b, 16, 16, 8, wmma::precision::tf32,
                       wmma::col_major> b[2];
        #pragma unroll
        for (int i = 0; i < 4; i++)
            wmma::load_matrix_sync(a[i], As + (wm * 64 + i * 16) * LDA + k, LDA);
        #pragma unroll
        for (int j = 0; j < 2; j++)
            wmma::load_matrix_sync(b[j], Bs + (wn * 32 + j * 16) * LDA + k, LDA);
        #pragma unroll
        for (int i = 0; i < 4; i++)
            #pragma unroll
            for (int j = 0; j < 2; j++)
                wmma::mma_sync(acc[i][j], a[i], b[j], acc[i][j]);
    }

    // Staged epilogue: frags -> smem (ld 132) -> coalesced float4 stores.
    __syncthreads();
    float* Os = smem;   // reuse; 128*132 <= 128*136
    #define LDO 132
    #pragma unroll
    for (int i = 0; i < 4; i++)
        #pragma unroll
        for (int j = 0; j < 2; j++)
            wmma::store_matrix_sync(
                Os + (wm * 64 + i * 16) * LDO + wn * 32 + j * 16,
                acc[i][j], LDO, wmma::mem_row_major);
    __syncthreads();

    #pragma unroll
    for (int it = 0; it < 16; it++) {
        int idx = tid + it * 256;
        int row = idx >> 5;
        int kq  = idx & 31;
        long long gm = m0 + row;
        if (gm < M)
            *(float4*)(z + gm * C_DIM + kq * 4) =
                *(const float4*)(Os + row * LDO + kq * 4);
    }
}

// ===========================================================================
// CSR build
// ===========================================================================
__global__ void k_zero_cnt(int n) {
    int i = blockIdx.x * blockDim.x + threadIdx.x;
    if (i < n) g_cnt[i] = 0;
}

__global__ void k_count(const int* __restrict__ rows, int E) {
    int e = blockIdx.x * blockDim.x + threadIdx.x;
    if (e < E) atomicAdd(&g_cnt[rows[e]], 1);
}

#define SCAN_T 1024
__global__ __launch_bounds__(SCAN_T)
void k_scan(int n, int E) {
    __shared__ int s[SCAN_T];
    const int t = threadIdx.x;
    const int chunk = (n + SCAN_T - 1) / SCAN_T;
    const int base = t * chunk;
    int sum = 0;
    for (int j = 0; j < chunk; j++) {
        int r = base + j;
        if (r < n) sum += g_cnt[r];
    }
    s[t] = sum;
    __syncthreads();
    #pragma unroll
    for (int d = 1; d < SCAN_T; d <<= 1) {
        int v = (t >= d) ? s[t - d] : 0;
        __syncthreads();
        s[t] += v;
        __syncthreads();
    }
    int run = s[t] - sum;
    for (int j = 0; j < chunk; j++) {
        int r = base + j;
        if (r < n) {
            g_rowptr[r] = run;
            g_ofs[r]    = run;
            run += g_cnt[r];
        }
    }
    if (t == 0) g_rowptr[n] = E;
}

__global__ void k_fill(const int* __restrict__ rows, const int* __restrict__ cols,
                       const float* __restrict__ vals, int E) {
    int e = blockIdx.x * blockDim.x + threadIdx.x;
    if (e >= E) return;
    int r = rows[e];
    int pos = atomicAdd(&g_ofs[r], 1);
    float2 ed;
    ed.x = __int_as_float(cols[e]);
    ed.y = vals[e];
    g_edata[pos] = ed;
}

// ===========================================================================
// Gather: one warp per output row, all 4 batches in registers, bias fused.
// ===========================================================================
__global__ __launch_bounds__(256)
void k_gather(const float* __restrict__ z, const float* __restrict__ bias,
              float* __restrict__ out, int N) {
    int gw   = (blockIdx.x * blockDim.x + threadIdx.x) >> 5;
    int lane = threadIdx.x & 31;
    if (gw >= N) return;
    const int r = gw;

    float4 acc0 = make_float4(0.f, 0.f, 0.f, 0.f);
    float4 acc1 = acc0, acc2 = acc0, acc3 = acc0;

    const int start = g_rowptr[r];
    const int end   = g_rowptr[r + 1];
    const size_t NB = (size_t)N * 32;

    for (int i = start; i < end; i++) {
        float2 ed = g_edata[i];
        int   c = __float_as_int(ed.x);
        float v = ed.y;
        const float4* src = (const float4*)z + (size_t)c * 32 + lane;
        float4 z0 = src[0];
        float4 z1 = src[NB];
        float4 z2 = src[2 * NB];
        float4 z3 = src[3 * NB];
        acc0.x = fmaf(v, z0.x, acc0.x); acc0.y = fmaf(v, z0.y, acc0.y);
        acc0.z = fmaf(v, z0.z, acc0.z); acc0.w = fmaf(v, z0.w, acc0.w);
        acc1.x = fmaf(v, z1.x, acc1.x); acc1.y = fmaf(v, z1.y, acc1.y);
        acc1.z = fmaf(v, z1.z, acc1.z); acc1.w = fmaf(v, z1.w, acc1.w);
        acc2.x = fmaf(v, z2.x, acc2.x); acc2.y = fmaf(v, z2.y, acc2.y);
        acc2.z = fmaf(v, z2.z, acc2.z); acc2.w = fmaf(v, z2.w, acc2.w);
        acc3.x = fmaf(v, z3.x, acc3.x); acc3.y = fmaf(v, z3.y, acc3.y);
        acc3.z = fmaf(v, z3.z, acc3.z); acc3.w = fmaf(v, z3.w, acc3.w);
    }

    float4 bv = ((const float4*)bias)[lane];
    acc0.x += bv.x; acc0.y += bv.y; acc0.z += bv.z; acc0.w += bv.w;
    acc1.x += bv.x; acc1.y += bv.y; acc1.z += bv.z; acc1.w += bv.w;
    acc2.x += bv.x; acc2.y += bv.y; acc2.z += bv.z; acc2.w += bv.w;
    acc3.x += bv.x; acc3.y += bv.y; acc3.z += bv.z; acc3.w += bv.w;

    float4* dst = (float4*)out + (size_t)r * 32 + lane;
    dst[0]      = acc0;
    dst[NB]     = acc1;
    dst[2 * NB] = acc2;
    dst[3 * NB] = acc3;
}

// ===========================================================================
extern "C" void kernel_launch(void* const* d_in, const int* in_sizes, int n_in,
                              void* d_out, int out_size) {
    const float* x    = (const float*)d_in[0];
    const int*   adj  = (const int*)d_in[1];
    const float* vals = (const float*)d_in[2];
    const float* W    = (const float*)d_in[3];
    const float* bias = (const float*)d_in[4];
    float* out = (float*)d_out;

    const int E = in_sizes[2];
    const int N = in_sizes[0] / (B_DIM * C_DIM);
    const int M = B_DIM * N;

    const int* rows = adj;
    const int* cols = adj + E;

    float* z;
    cudaGetSymbolAddress((void**)&z, g_z);

    // CSR build
    k_zero_cnt<<<(N + 255) / 256, 256>>>(N);
    k_count<<<(E + 255) / 256, 256>>>(rows, E);
    k_scan<<<1, SCAN_T>>>(N, E);
    k_fill<<<(E + 255) / 256, 256>>>(rows, cols, vals, E);

    // wmma tf32 GEMM
    static bool attr_set = false;
    if (!attr_set) {
        cudaFuncSetAttribute(gemm_wmma, cudaFuncAttributeMaxDynamicSharedMemorySize,
                             GEMM_SMEM);
        attr_set = true;
    }
    int gtiles = (M + 127) / 128;
    gemm_wmma<<<gtiles, 256, GEMM_SMEM>>>(x, W, z, M);

    // Gather with fused bias
    int blocks = (N * 32 + 255) / 256;
    k_gather<<<blocks, 256>>>(z, bias, out, N);
}

// round 5
// speedup vs baseline: 2.8424x; 1.1291x over previous
#include <cuda_runtime.h>
#include <cuda_fp16.h>
#include <mma.h>
#include <cstdint>

using namespace nvcuda;

// GraphConvolution: y = A @ (x @ W^T) + b
//   x: (B=4, N=50000, C=128) f32, adj: (2, E=800000) i32, vals: (E,) f32
//   W: (128,128) f32, b: (128,) f32, out: (B,N,128) f32

#define C_DIM 128
#define B_DIM 4
#define N_ROWS 50000
#define E_MAX  800000

// z stored fp16, node-major: z_h[n][b][c] -> 128 uint2 (512 halfs) per node.
__device__ uint2  g_zh[(size_t)N_ROWS * 128];
__device__ int    g_cnt[N_ROWS];
__device__ int    g_rowptr[N_ROWS + 1];
__device__ int    g_ofs[N_ROWS];
__device__ float2 g_edata[E_MAX];

// ===========================================================================
// GEMM z = x @ W^T via wmma tf32 (m16n16k8), output fp16 node-major.
// CTA tile: 128(m) x 128(n) x 128(k). 8 warps 2x4; each 64x32 (4x2 frags).
// ===========================================================================
#define LDA 136
#define LDO 132
#define GEMM_SMEM (2 * 128 * LDA * 4)   // 139264 bytes

__global__ __launch_bounds__(256, 1)
void gemm_wmma(const float* __restrict__ x, const float* __restrict__ W,
               int M, int N) {
    extern __shared__ float smem[];
    float* As = smem;               // [128][LDA]
    float* Bs = smem + 128 * LDA;   // [128][LDA]

    const int tid = threadIdx.x;
    const int wid = tid >> 5;
    const long long m0 = (long long)blockIdx.x * 128;

    #pragma unroll
    for (int it = 0; it < 16; it++) {
        int idx = tid + it * 256;
        int row = idx >> 5;
        int kq  = idx & 31;
        long long gm = m0 + row; if (gm >= M) gm = M - 1;
        float4 v = *(const float4*)(x + gm * C_DIM + kq * 4);
        v.x = wmma::__float_to_tf32(v.x); v.y = wmma::__float_to_tf32(v.y);
        v.z = wmma::__float_to_tf32(v.z); v.w = wmma::__float_to_tf32(v.w);
        *(float4*)(As + row * LDA + kq * 4) = v;
    }
    #pragma unroll
    for (int it = 0; it < 16; it++) {
        int idx = tid + it * 256;
        int row = idx >> 5;
        int kq  = idx & 31;
        float4 v = *(const float4*)(W + row * C_DIM + kq * 4);
        v.x = wmma::__float_to_tf32(v.x); v.y = wmma::__float_to_tf32(v.y);
        v.z = wmma::__float_to_tf32(v.z); v.w = wmma::__float_to_tf32(v.w);
        *(float4*)(Bs + row * LDA + kq * 4) = v;
    }
    __syncthreads();

    const int wm = wid & 1;
    const int wn = wid >> 1;

    wmma::fragment<wmma::accumulator, 16, 16, 8, float> acc[4][2];
    #pragma unroll
    for (int i = 0; i < 4; i++)
        #pragma unroll
        for (int j = 0; j < 2; j++) wmma::fill_fragment(acc[i][j], 0.0f);

    #pragma unroll
    for (int ks = 0; ks < 16; ks++) {
        const int k = ks * 8;
        wmma::fragment<wmma::matrix_a, 16, 16, 8, wmma::precision::tf32,
                       wmma::row_major> a[4];
        wmma::fragment<wmma::matrix_b, 16, 16, 8, wmma::precision::tf32,
                       wmma::col_major> b[2];
        #pragma unroll
        for (int i = 0; i < 4; i++)
            wmma::load_matrix_sync(a[i], As + (wm * 64 + i * 16) * LDA + k, LDA);
        #pragma unroll
        for (int j = 0; j < 2; j++)
            wmma::load_matrix_sync(b[j], Bs + (wn * 32 + j * 16) * LDA + k, LDA);
        #pragma unroll
        for (int i = 0; i < 4; i++)
            #pragma unroll
            for (int j = 0; j < 2; j++)
                wmma::mma_sync(acc[i][j], a[i], b[j], acc[i][j]);
    }

    // Epilogue: frags -> smem -> fp16 node-major z.
    __syncthreads();
    float* Os = smem;
    #pragma unroll
    for (int i = 0; i < 4; i++)
        #pragma unroll
        for (int j = 0; j < 2; j++)
            wmma::store_matrix_sync(
                Os + (wm * 64 + i * 16) * LDO + wn * 32 + j * 16,
                acc[i][j], LDO, wmma::mem_row_major);
    __syncthreads();

    #pragma unroll
    for (int it = 0; it < 16; it++) {
        int idx = tid + it * 256;
        int row = idx >> 5;
        int q   = idx & 31;                 // uint2 (4-half) index within row
        long long gm = m0 + row;
        if (gm < M) {
            float4 v = *(const float4*)(Os + row * LDO + q * 4);
            __half2 h0 = __floats2half2_rn(v.x, v.y);
            __half2 h1 = __floats2half2_rn(v.z, v.w);
            int b = (int)(gm / N);
            int n = (int)(gm % N);
            uint2 pack;
            pack.x = *(uint32_t*)&h0;
            pack.y = *(uint32_t*)&h1;
            g_zh[(size_t)n * 128 + b * 32 + q] = pack;
        }
    }
}

// ===========================================================================
// CSR build
// ===========================================================================
__global__ void k_zero_cnt(int n) {
    int i = blockIdx.x * blockDim.x + threadIdx.x;
    if (i < n) g_cnt[i] = 0;
}

__global__ void k_count(const int* __restrict__ rows, int E) {
    int e = blockIdx.x * blockDim.x + threadIdx.x;
    if (e < E) atomicAdd(&g_cnt[rows[e]], 1);
}

#define SCAN_T 1024
__global__ __launch_bounds__(SCAN_T)
void k_scan(int n, int E) {
    __shared__ int s[SCAN_T];
    const int t = threadIdx.x;
    const int chunk = (n + SCAN_T - 1) / SCAN_T;
    const int base = t * chunk;
    int sum = 0;
    for (int j = 0; j < chunk; j++) {
        int r = base + j;
        if (r < n) sum += g_cnt[r];
    }
    s[t] = sum;
    __syncthreads();
    #pragma unroll
    for (int d = 1; d < SCAN_T; d <<= 1) {
        int v = (t >= d) ? s[t - d] : 0;
        __syncthreads();
        s[t] += v;
        __syncthreads();
    }
    int run = s[t] - sum;
    for (int j = 0; j < chunk; j++) {
        int r = base + j;
        if (r < n) {
            g_rowptr[r] = run;
            g_ofs[r]    = run;
            run += g_cnt[r];
        }
    }
    if (t == 0) g_rowptr[n] = E;
}

__global__ void k_fill(const int* __restrict__ rows, const int* __restrict__ cols,
                       const float* __restrict__ vals, int E) {
    int e = blockIdx.x * blockDim.x + threadIdx.x;
    if (e >= E) return;
    int r = rows[e];
    int pos = atomicAdd(&g_ofs[r], 1);
    float2 ed;
    ed.x = __int_as_float(cols[e]);
    ed.y = vals[e];
    g_edata[pos] = ed;
}

// ===========================================================================
// Gather: one warp per output row. Per edge the warp reads a contiguous 1KB
// fp16 block (4 batches x 256B); lane covers channels [lane*4, lane*4+4).
// Accumulate fp32, bias fused, fp32 output.
// ===========================================================================
__global__ __launch_bounds__(256)
void k_gather(const float* __restrict__ bias, float* __restrict__ out, int N) {
    int gw   = (blockIdx.x * blockDim.x + threadIdx.x) >> 5;
    int lane = threadIdx.x & 31;
    if (gw >= N) return;
    const int r = gw;

    float4 acc0 = make_float4(0.f, 0.f, 0.f, 0.f);
    float4 acc1 = acc0, acc2 = acc0, acc3 = acc0;

    const int start = g_rowptr[r];
    const int end   = g_rowptr[r + 1];

    for (int i = start; i < end; i++) {
        float2 ed = g_edata[i];
        int   c = __float_as_int(ed.x);
        float v = ed.y;
        const uint2* src = g_zh + (size_t)c * 128;
        uint2 p0 = src[lane];
        uint2 p1 = src[lane + 32];
        uint2 p2 = src[lane + 64];
        uint2 p3 = src[lane + 96];

        float2 a, b;
        a = __half22float2(*(__half2*)&p0.x); b = __half22float2(*(__half2*)&p0.y);
        acc0.x = fmaf(v, a.x, acc0.x); acc0.y = fmaf(v, a.y, acc0.y);
        acc0.z = fmaf(v, b.x, acc0.z); acc0.w = fmaf(v, b.y, acc0.w);
        a = __half22float2(*(__half2*)&p1.x); b = __half22float2(*(__half2*)&p1.y);
        acc1.x = fmaf(v, a.x, acc1.x); acc1.y = fmaf(v, a.y, acc1.y);
        acc1.z = fmaf(v, b.x, acc1.z); acc1.w = fmaf(v, b.y, acc1.w);
        a = __half22float2(*(__half2*)&p2.x); b = __half22float2(*(__half2*)&p2.y);
        acc2.x = fmaf(v, a.x, acc2.x); acc2.y = fmaf(v, a.y, acc2.y);
        acc2.z = fmaf(v, b.x, acc2.z); acc2.w = fmaf(v, b.y, acc2.w);
        a = __half22float2(*(__half2*)&p3.x); b = __half22float2(*(__half2*)&p3.y);
        acc3.x = fmaf(v, a.x, acc3.x); acc3.y = fmaf(v, a.y, acc3.y);
        acc3.z = fmaf(v, b.x, acc3.z); acc3.w = fmaf(v, b.y, acc3.w);
    }

    float4 bv = ((const float4*)bias)[lane];
    acc0.x += bv.x; acc0.y += bv.y; acc0.z += bv.z; acc0.w += bv.w;
    acc1.x += bv.x; acc1.y += bv.y; acc1.z += bv.z; acc1.w += bv.w;
    acc2.x += bv.x; acc2.y += bv.y; acc2.z += bv.z; acc2.w += bv.w;
    acc3.x += bv.x; acc3.y += bv.y; acc3.z += bv.z; acc3.w += bv.w;

    const size_t NB = (size_t)N * 32;   // float4 units per batch
    float4* dst = (float4*)out + (size_t)r * 32 + lane;
    dst[0]      = acc0;
    dst[NB]     = acc1;
    dst[2 * NB] = acc2;
    dst[3 * NB] = acc3;
}

// ===========================================================================
extern "C" void kernel_launch(void* const* d_in, const int* in_sizes, int n_in,
                              void* d_out, int out_size) {
    const float* x    = (const float*)d_in[0];
    const int*   adj  = (const int*)d_in[1];
    const float* vals = (const float*)d_in[2];
    const float* W    = (const float*)d_in[3];
    const float* bias = (const float*)d_in[4];
    float* out = (float*)d_out;

    const int E = in_sizes[2];
    const int N = in_sizes[0] / (B_DIM * C_DIM);
    const int M = B_DIM * N;

    const int* rows = adj;
    const int* cols = adj + E;

    // CSR build
    k_zero_cnt<<<(N + 255) / 256, 256>>>(N);
    k_count<<<(E + 255) / 256, 256>>>(rows, E);
    k_scan<<<1, SCAN_T>>>(N, E);
    k_fill<<<(E + 255) / 256, 256>>>(rows, cols, vals, E);

    // wmma tf32 GEMM -> fp16 node-major z
    static bool attr_set = false;
    if (!attr_set) {
        cudaFuncSetAttribute(gemm_wmma, cudaFuncAttributeMaxDynamicSharedMemorySize,
                             GEMM_SMEM);
        attr_set = true;
    }
    int gtiles = (M + 127) / 128;
    gemm_wmma<<<gtiles, 256, GEMM_SMEM>>>(x, W, M, N);

    // Gather with fused bias
    int blocks = (N * 32 + 255) / 256;
    k_gather<<<blocks, 256>>>(bias, out, N);
}

// round 6
// speedup vs baseline: 2.8461x; 1.0013x over previous
#include <cuda_runtime.h>
#include <cuda_fp16.h>
#include <mma.h>
#include <cstdint>

using namespace nvcuda;

// GraphConvolution: y = A @ (x @ W^T) + b
//   x: (B=4, N=50000, C=128) f32, adj: (2, E=800000) i32, vals: (E,) f32
//   W: (128,128) f32, b: (128,) f32, out: (B,N,128) f32

#define C_DIM 128
#define B_DIM 4
#define N_ROWS 50000
#define E_MAX  800000

// z stored fp16, node-major: z_h[n][b][c] -> 128 uint2 (512 halfs) per node.
__device__ uint2  g_zh[(size_t)N_ROWS * 128];
__device__ int    g_cnt[N_ROWS];
__device__ int    g_rowptr[N_ROWS + 1];
__device__ int    g_ofs[N_ROWS];
__device__ float2 g_edata[E_MAX];

// ===========================================================================
// GEMM z = x @ W^T via wmma tf32 (m16n16k8), output fp16 node-major.
// CTA tile: 128(m) x 128(n) x 128(k). 8 warps 2x4; each 64x32 (4x2 frags).
// x read with __ldcs (read-once, keep L2 for z).
// ===========================================================================
#define LDA 136
#define LDO 132
#define GEMM_SMEM (2 * 128 * LDA * 4)   // 139264 bytes

__global__ __launch_bounds__(256, 1)
void gemm_wmma(const float* __restrict__ x, const float* __restrict__ W,
               int M, int N) {
    extern __shared__ float smem[];
    float* As = smem;               // [128][LDA]
    float* Bs = smem + 128 * LDA;   // [128][LDA]

    const int tid = threadIdx.x;
    const int wid = tid >> 5;
    const long long m0 = (long long)blockIdx.x * 128;

    #pragma unroll
    for (int it = 0; it < 16; it++) {
        int idx = tid + it * 256;
        int row = idx >> 5;
        int kq  = idx & 31;
        long long gm = m0 + row; if (gm >= M) gm = M - 1;
        float4 v = __ldcs((const float4*)(x + gm * C_DIM + kq * 4));
        v.x = wmma::__float_to_tf32(v.x); v.y = wmma::__float_to_tf32(v.y);
        v.z = wmma::__float_to_tf32(v.z); v.w = wmma::__float_to_tf32(v.w);
        *(float4*)(As + row * LDA + kq * 4) = v;
    }
    #pragma unroll
    for (int it = 0; it < 16; it++) {
        int idx = tid + it * 256;
        int row = idx >> 5;
        int kq  = idx & 31;
        float4 v = *(const float4*)(W + row * C_DIM + kq * 4);
        v.x = wmma::__float_to_tf32(v.x); v.y = wmma::__float_to_tf32(v.y);
        v.z = wmma::__float_to_tf32(v.z); v.w = wmma::__float_to_tf32(v.w);
        *(float4*)(Bs + row * LDA + kq * 4) = v;
    }
    __syncthreads();

    const int wm = wid & 1;
    const int wn = wid >> 1;

    wmma::fragment<wmma::accumulator, 16, 16, 8, float> acc[4][2];
    #pragma unroll
    for (int i = 0; i < 4; i++)
        #pragma unroll
        for (int j = 0; j < 2; j++) wmma::fill_fragment(acc[i][j], 0.0f);

    #pragma unroll
    for (int ks = 0; ks < 16; ks++) {
        const int k = ks * 8;
        wmma::fragment<wmma::matrix_a, 16, 16, 8, wmma::precision::tf32,
                       wmma::row_major> a[4];
        wmma::fragment<wmma::matrix_b, 16, 16, 8, wmma::precision::tf32,
                       wmma::col_major> b[2];
        #pragma unroll
        for (int i = 0; i < 4; i++)
            wmma::load_matrix_sync(a[i], As + (wm * 64 + i * 16) * LDA + k, LDA);
        #pragma unroll
        for (int j = 0; j < 2; j++)
            wmma::load_matrix_sync(b[j], Bs + (wn * 32 + j * 16) * LDA + k, LDA);
        #pragma unroll
        for (int i = 0; i < 4; i++)
            #pragma unroll
            for (int j = 0; j < 2; j++)
                wmma::mma_sync(acc[i][j], a[i], b[j], acc[i][j]);
    }

    // Epilogue: frags -> smem -> fp16 node-major z (write-back: wants L2).
    __syncthreads();
    float* Os = smem;
    #pragma unroll
    for (int i = 0; i < 4; i++)
        #pragma unroll
        for (int j = 0; j < 2; j++)
            wmma::store_matrix_sync(
                Os + (wm * 64 + i * 16) * LDO + wn * 32 + j * 16,
                acc[i][j], LDO, wmma::mem_row_major);
    __syncthreads();

    #pragma unroll
    for (int it = 0; it < 16; it++) {
        int idx = tid + it * 256;
        int row = idx >> 5;
        int q   = idx & 31;
        long long gm = m0 + row;
        if (gm < M) {
            float4 v = *(const float4*)(Os + row * LDO + q * 4);
            __half2 h0 = __floats2half2_rn(v.x, v.y);
            __half2 h1 = __floats2half2_rn(v.z, v.w);
            int b = (int)(gm / N);
            int n = (int)(gm % N);
            uint2 pack;
            pack.x = *(uint32_t*)&h0;
            pack.y = *(uint32_t*)&h1;
            g_zh[(size_t)n * 128 + b * 32 + q] = pack;
        }
    }
}

// ===========================================================================
// CSR build
// ===========================================================================
__global__ void k_zero_cnt(int n) {
    int i = blockIdx.x * blockDim.x + threadIdx.x;
    if (i < n) g_cnt[i] = 0;
}

__global__ void k_count(const int* __restrict__ rows, int E) {
    int e = blockIdx.x * blockDim.x + threadIdx.x;
    if (e < E) atomicAdd(&g_cnt[rows[e]], 1);
}

#define SCAN_T 1024
__global__ __launch_bounds__(SCAN_T)
void k_scan(int n, int E) {
    __shared__ int s[SCAN_T];
    const int t = threadIdx.x;
    const int chunk = (n + SCAN_T - 1) / SCAN_T;
    const int base = t * chunk;
    int sum = 0;
    for (int j = 0; j < chunk; j++) {
        int r = base + j;
        if (r < n) sum += g_cnt[r];
    }
    s[t] = sum;
    __syncthreads();
    #pragma unroll
    for (int d = 1; d < SCAN_T; d <<= 1) {
        int v = (t >= d) ? s[t - d] : 0;
        __syncthreads();
        s[t] += v;
        __syncthreads();
    }
    int run = s[t] - sum;
    for (int j = 0; j < chunk; j++) {
        int r = base + j;
        if (r < n) {
            g_rowptr[r] = run;
            g_ofs[r]    = run;
            run += g_cnt[r];
        }
    }
    if (t == 0) g_rowptr[n] = E;
}

__global__ void k_fill(const int* __restrict__ rows, const int* __restrict__ cols,
                       const float* __restrict__ vals, int E) {
    int e = blockIdx.x * blockDim.x + threadIdx.x;
    if (e >= E) return;
    int r = rows[e];
    int pos = atomicAdd(&g_ofs[r], 1);
    float2 ed;
    ed.x = __int_as_float(cols[e]);
    ed.y = vals[e];
    g_edata[pos] = ed;
}

// ===========================================================================
// Gather: one warp per output row, 2-way unrolled edge loop for MLP,
// fp32 accumulation, bias fused, streaming (__stcs) fp32 output.
// ===========================================================================
__device__ __forceinline__ void accum_node(const uint2* __restrict__ src,
                                           int lane, float v,
                                           float4& a0, float4& a1,
                                           float4& a2, float4& a3) {
    uint2 p0 = __ldg(src + lane);
    uint2 p1 = __ldg(src + lane + 32);
    uint2 p2 = __ldg(src + lane + 64);
    uint2 p3 = __ldg(src + lane + 96);
    float2 fa, fb;
    fa = __half22float2(*(__half2*)&p0.x); fb = __half22float2(*(__half2*)&p0.y);
    a0.x = fmaf(v, fa.x, a0.x); a0.y = fmaf(v, fa.y, a0.y);
    a0.z = fmaf(v, fb.x, a0.z); a0.w = fmaf(v, fb.y, a0.w);
    fa = __half22float2(*(__half2*)&p1.x); fb = __half22float2(*(__half2*)&p1.y);
    a1.x = fmaf(v, fa.x, a1.x); a1.y = fmaf(v, fa.y, a1.y);
    a1.z = fmaf(v, fb.x, a1.z); a1.w = fmaf(v, fb.y, a1.w);
    fa = __half22float2(*(__half2*)&p2.x); fb = __half22float2(*(__half2*)&p2.y);
    a2.x = fmaf(v, fa.x, a2.x); a2.y = fmaf(v, fa.y, a2.y);
    a2.z = fmaf(v, fb.x, a2.z); a2.w = fmaf(v, fb.y, a2.w);
    fa = __half22float2(*(__half2*)&p3.x); fb = __half22float2(*(__half2*)&p3.y);
    a3.x = fmaf(v, fa.x, a3.x); a3.y = fmaf(v, fa.y, a3.y);
    a3.z = fmaf(v, fb.x, a3.z); a3.w = fmaf(v, fb.y, a3.w);
}

__global__ __launch_bounds__(256)
void k_gather(const float* __restrict__ bias, float* __restrict__ out, int N) {
    int gw   = (blockIdx.x * blockDim.x + threadIdx.x) >> 5;
    int lane = threadIdx.x & 31;
    if (gw >= N) return;
    const int r = gw;

    float4 acc0 = make_float4(0.f, 0.f, 0.f, 0.f);
    float4 acc1 = acc0, acc2 = acc0, acc3 = acc0;
    float4 bcc0 = acc0, bcc1 = acc0, bcc2 = acc0, bcc3 = acc0;

    const int start = g_rowptr[r];
    const int end   = g_rowptr[r + 1];

    int i = start;
    // 2-way unroll: both edges' records + all 8 z-blocks issued before FMAs.
    for (; i + 2 <= end; i += 2) {
        float2 e0 = __ldg(&g_edata[i]);
        float2 e1 = __ldg(&g_edata[i + 1]);
        const uint2* s0 = g_zh + (size_t)__float_as_int(e0.x) * 128;
        const uint2* s1 = g_zh + (size_t)__float_as_int(e1.x) * 128;
        accum_node(s0, lane, e0.y, acc0, acc1, acc2, acc3);
        accum_node(s1, lane, e1.y, bcc0, bcc1, bcc2, bcc3);
    }
    if (i < end) {
        float2 e0 = __ldg(&g_edata[i]);
        const uint2* s0 = g_zh + (size_t)__float_as_int(e0.x) * 128;
        accum_node(s0, lane, e0.y, acc0, acc1, acc2, acc3);
    }

    float4 bv = ((const float4*)bias)[lane];
    acc0.x += bcc0.x + bv.x; acc0.y += bcc0.y + bv.y;
    acc0.z += bcc0.z + bv.z; acc0.w += bcc0.w + bv.w;
    acc1.x += bcc1.x + bv.x; acc1.y += bcc1.y + bv.y;
    acc1.z += bcc1.z + bv.z; acc1.w += bcc1.w + bv.w;
    acc2.x += bcc2.x + bv.x; acc2.y += bcc2.y + bv.y;
    acc2.z += bcc2.z + bv.z; acc2.w += bcc2.w + bv.w;
    acc3.x += bcc3.x + bv.x; acc3.y += bcc3.y + bv.y;
    acc3.z += bcc3.z + bv.z; acc3.w += bcc3.w + bv.w;

    const size_t NB = (size_t)N * 32;   // float4 units per batch
    float4* dst = (float4*)out + (size_t)r * 32 + lane;
    __stcs(dst,          acc0);
    __stcs(dst + NB,     acc1);
    __stcs(dst + 2 * NB, acc2);
    __stcs(dst + 3 * NB, acc3);
}

// ===========================================================================
extern "C" void kernel_launch(void* const* d_in, const int* in_sizes, int n_in,
                              void* d_out, int out_size) {
    const float* x    = (const float*)d_in[0];
    const int*   adj  = (const int*)d_in[1];
    const float* vals = (const float*)d_in[2];
    const float* W    = (const float*)d_in[3];
    const float* bias = (const float*)d_in[4];
    float* out = (float*)d_out;

    const int E = in_sizes[2];
    const int N = in_sizes[0] / (B_DIM * C_DIM);
    const int M = B_DIM * N;

    const int* rows = adj;
    const int* cols = adj + E;

    // CSR build
    k_zero_cnt<<<(N + 255) / 256, 256>>>(N);
    k_count<<<(E + 255) / 256, 256>>>(rows, E);
    k_scan<<<1, SCAN_T>>>(N, E);
    k_fill<<<(E + 255) / 256, 256>>>(rows, cols, vals, E);

    // wmma tf32 GEMM -> fp16 node-major z
    static bool attr_set = false;
    if (!attr_set) {
        cudaFuncSetAttribute(gemm_wmma, cudaFuncAttributeMaxDynamicSharedMemorySize,
                             GEMM_SMEM);
        attr_set = true;
    }
    int gtiles = (M + 127) / 128;
    gemm_wmma<<<gtiles, 256, GEMM_SMEM>>>(x, W, M, N);

    // Gather with fused bias
    int blocks = (N * 32 + 255) / 256;
    k_gather<<<blocks, 256>>>(bias, out, N);
}